// round 2
// baseline (speedup 1.0000x reference)
#include <cuda_runtime.h>
#include <math.h>

#define Hh 2048
#define Wd 2048
#define MASKM 2047
#define Kk 16
#define Pp 15

// scratch (static device globals — no allocation)
__device__ float g_win[Hh * Wd];
__device__ int   g_n;
__device__ int   g_osy[Kk];
__device__ int   g_osx[Kk];
__device__ float g_ow[Kk];
__device__ float g_C;

// ---------------------------------------------------------------------------
// Kernel 0: reduce patterns -> constant C; dedupe shift offsets with weights
// ---------------------------------------------------------------------------
__global__ void k_prep(const float* __restrict__ patterns,
                       const float* __restrict__ vectors) {
    __shared__ float red[256];
    int t = threadIdx.x;
    float s = 0.f;
    for (int i = t; i < Kk * Pp * Pp; i += 256) s += patterns[i];
    red[t] = s;
    __syncthreads();
    for (int off = 128; off > 0; off >>= 1) {
        if (t < off) red[t] += red[t + off];
        __syncthreads();
    }
    if (t == 0) {
        g_C = ((float)Kk - red[0] / (float)(Pp * Pp)) / (float)(Kk - 1);
        // dedupe offsets
        int n = 0;
        int sy[Kk], sx[Kk]; float w[Kk];
        for (int k = 0; k < Kk; k++) {
            int oy = (int)floorf(vectors[2 * k]);
            int ox = (int)floorf(vectors[2 * k + 1]);
            int ny = oy & MASKM; if (ny >= 1024) ny -= 2048;
            int nx = ox & MASKM; if (nx >= 1024) nx -= 2048;
            int found = -1;
            for (int m = 0; m < n; m++)
                if (sy[m] == ny && sx[m] == nx) { found = m; break; }
            if (found >= 0) w[found] += 1.0f;
            else { sy[n] = ny; sx[n] = nx; w[n] = 1.0f; n++; }
        }
        g_n = n;
        for (int m = 0; m < n; m++) {
            g_osy[m] = sy[m]; g_osx[m] = sx[m]; g_ow[m] = w[m];
        }
    }
}

// ---------------------------------------------------------------------------
// Kernel 1: fused separable 15x15 box-sum (zero-padded above/left).
// win[i][j] = sum_{a=i-15..i-1, b=j-15..j-1} img[a][b]  (zero outside)
// Tile: 128 rows x 64 cols of win per block. Rowsum staged in SMEM
// (143 x 64, row stride 65 for conflict-free column reads).
// grid = (32, 16), 256 threads.
// ---------------------------------------------------------------------------
__global__ void __launch_bounds__(256) k_box(const float* __restrict__ img) {
    __shared__ float rs[143 * 65];

    int t = threadIdx.x;
    int j0 = blockIdx.x * 64;    // win col base
    int i0 = blockIdx.y * 128;   // win row base

    // ---- phase 1: horizontal sliding sum into rs ----
    // rs row r (0..142) corresponds to img row (i0-15+r).
    // rs[r][c] = rowsum[i0-15+r][j0+c] = sum img[.][j0+c-15 .. j0+c-1]
    for (int tt = t; tt < 143 * 8; tt += 256) {
        int r   = tt >> 3;
        int seg = tt & 7;
        int arow = i0 - 15 + r;
        int jb = j0 + seg * 8;       // first of 8 output cols
        float o[8];
        if (arow < 0) {
            #pragma unroll
            for (int c = 0; c < 8; c++) o[c] = 0.f;
        } else {
            const float* row = img + (size_t)arow * Wd;
            float v[24];  // img cols jb-16 .. jb+7
            if (jb >= 16) {
                const float4* p = (const float4*)(row + jb - 16);
                #pragma unroll
                for (int q = 0; q < 6; q++) {
                    float4 f = __ldg(p + q);
                    v[4 * q + 0] = f.x; v[4 * q + 1] = f.y;
                    v[4 * q + 2] = f.z; v[4 * q + 3] = f.w;
                }
            } else {
                #pragma unroll
                for (int x = 0; x < 24; x++) {
                    int c = jb - 16 + x;
                    v[x] = (c >= 0) ? __ldg(row + c) : 0.f;
                }
            }
            float s = 0.f;
            #pragma unroll
            for (int x = 1; x <= 15; x++) s += v[x];
            o[0] = s;
            #pragma unroll
            for (int c = 1; c < 8; c++) { s += v[15 + c] - v[c]; o[c] = s; }
        }
        float* dst = rs + r * 65 + seg * 8;
        #pragma unroll
        for (int c = 0; c < 8; c++) dst[c] = o[c];
    }
    __syncthreads();

    // ---- phase 2: vertical sliding sum, write win tile ----
    // win[i0+R][j0+col] = sum_{r=R..R+14} rs[r][col]
    int col = t & 63;
    int R0  = (t >> 6) * 32;   // 0,32,64,96
    const float* cp = rs + col;
    float s = 0.f;
    #pragma unroll
    for (int r = 0; r < 15; r++) s += cp[(R0 + r) * 65];
    float* outp = g_win + (size_t)(i0 + R0) * Wd + j0 + col;
    #pragma unroll
    for (int rr = 0; rr < 32; rr++) {
        outp[(size_t)rr * Wd] = s;
        if (rr < 31)
            s += cp[(R0 + rr + 15) * 65] - cp[(R0 + rr) * 65];
    }
}

// ---------------------------------------------------------------------------
// Kernel 2: out[i,j] = C + (1/3375) * sum_m w_m * win[(i-sy_m)&M][(j-sx_m)&M]
// Tile 32 rows x 128 cols; halo +-8 staged in SMEM (48 x 144).
// grid = (16, 64), 256 threads; thread = 1 col x 16 rows.
// ---------------------------------------------------------------------------
__global__ void __launch_bounds__(256, 6) k_gather(float* __restrict__ out) {
    __shared__ float tile[48][144];
    __shared__ int ssy[Kk], ssx[Kk];
    __shared__ float sw[Kk];
    __shared__ int sn;
    __shared__ float sC;

    int t = threadIdx.x;
    int j0 = blockIdx.x * 128;
    int i0 = blockIdx.y * 32;

    if (t < Kk) { ssy[t] = g_osy[t]; ssx[t] = g_osx[t]; sw[t] = g_ow[t]; }
    if (t == 0) { sn = g_n; sC = g_C; }

    // stage 48 x 144 halo tile, float4 (alignment safe: j0-8 ≡ 0 mod 4,
    // aligned gc<=2044 so a float4 never crosses the wrap)
    for (int idx = t; idx < 48 * 36; idx += 256) {
        int u  = idx / 36;
        int vq = idx - u * 36;
        int gr = (i0 - 8 + u) & MASKM;
        int gc = (j0 - 8 + 4 * vq) & MASKM;
        float4 f = __ldg((const float4*)(g_win + (size_t)gr * Wd + gc));
        *(float4*)&tile[u][4 * vq] = f;
    }
    __syncthreads();

    int tx = t & 127;          // column
    int R0 = (t >> 7) * 16;    // 0 or 16

    float acc[16];
    #pragma unroll
    for (int rr = 0; rr < 16; rr++) acc[rr] = 0.f;

    int n = sn;
    for (int m = 0; m < n; m++) {
        int sy = ssy[m], sx = ssx[m];
        float w = sw[m];
        if (sy >= -8 && sy <= 8 && sx >= -8 && sx <= 8) {
            const float* p = &tile[R0 + 8 - sy][8 - sx + tx];
            #pragma unroll
            for (int rr = 0; rr < 16; rr++) acc[rr] += w * p[rr * 144];
        } else {
            int gc = (j0 + tx - sx) & MASKM;
            #pragma unroll 1
            for (int rr = 0; rr < 16; rr++) {
                int gr = (i0 + R0 + rr - sy) & MASKM;
                acc[rr] += w * __ldg(g_win + (size_t)gr * Wd + gc);
            }
        }
    }

    const float scale = 1.0f / 3375.0f;
    float c = sC;
    float* op = out + (size_t)(i0 + R0) * Wd + j0 + tx;
    #pragma unroll
    for (int rr = 0; rr < 16; rr++)
        op[(size_t)rr * Wd] = c + scale * acc[rr];
}

// ---------------------------------------------------------------------------
extern "C" void kernel_launch(void* const* d_in, const int* in_sizes, int n_in,
                              void* d_out, int out_size) {
    const float* x        = (const float*)d_in[0];  // (1,1,2048,2048)
    const float* patterns = (const float*)d_in[1];  // (16,15,15)
    const float* vectors  = (const float*)d_in[2];  // (16,2)
    float* out = (float*)d_out;                     // (2048,2048)

    k_prep<<<1, 256>>>(patterns, vectors);
    k_box<<<dim3(32, 16), 256>>>(x);
    k_gather<<<dim3(16, 64), 256>>>(out);
}

// round 3
// speedup vs baseline: 1.0356x; 1.0356x over previous
#include <cuda_runtime.h>
#include <math.h>

#define Hh 2048
#define Wd 2048
#define MASKM 2047
#define Kk 16
#define Pp 15

// scratch (static device globals — no allocation)
__device__ float g_rowsum[Hh * Wd];
__device__ float g_win[Hh * Wd];
__device__ int   g_n;
__device__ int   g_osy[Kk];
__device__ int   g_osx[Kk];
__device__ float g_ow[Kk];
__device__ float g_C;

// ---------------------------------------------------------------------------
// Kernel 0: reduce patterns -> constant C; dedupe shift offsets (parallel
// global loads, serial dedupe only on SMEM data).
// ---------------------------------------------------------------------------
__global__ void __launch_bounds__(1024) k_prep(const float* __restrict__ patterns,
                                               const float* __restrict__ vectors) {
    __shared__ float red[1024];
    __shared__ int shy[Kk], shx[Kk];
    int t = threadIdx.x;

    // parallel load of vectors (32 floats) -> per-k offsets
    if (t < Kk) {
        float vy = __ldg(vectors + 2 * t);
        float vx = __ldg(vectors + 2 * t + 1);
        int oy = (int)floorf(vy);
        int ox = (int)floorf(vx);
        int ny = oy & MASKM; if (ny >= 1024) ny -= 2048;
        int nx = ox & MASKM; if (nx >= 1024) nx -= 2048;
        shy[t] = ny; shx[t] = nx;
    }

    // pattern reduction: 3600 floats = 900 float4
    float s = 0.f;
    if (t < 900) {
        float4 f = __ldg((const float4*)patterns + t);
        s = f.x + f.y + f.z + f.w;
    }
    red[t] = s;
    __syncthreads();
    for (int off = 512; off > 0; off >>= 1) {
        if (t < off) red[t] += red[t + off];
        __syncthreads();
    }

    if (t == 0) {
        g_C = ((float)Kk - red[0] / (float)(Pp * Pp)) / (float)(Kk - 1);
        // dedupe from SMEM (ALU only)
        int n = 0;
        int sy[Kk], sx[Kk]; float w[Kk];
        #pragma unroll
        for (int k = 0; k < Kk; k++) {
            int ny = shy[k], nx = shx[k];
            int found = -1;
            for (int m = 0; m < n; m++)
                if (sy[m] == ny && sx[m] == nx) { found = m; break; }
            if (found >= 0) w[found] += 1.0f;
            else { sy[n] = ny; sx[n] = nx; w[n] = 1.0f; n++; }
        }
        g_n = n;
        for (int m = 0; m < n; m++) {
            g_osy[m] = sy[m]; g_osx[m] = sx[m]; g_ow[m] = w[m];
        }
    }
}

// ---------------------------------------------------------------------------
// Kernel A: horizontal sliding 15-sum.
// rowsum[i][j] = sum_{t=1..15} img[i][j-t]  (zero for j-t < 0)
// One block per row, 256 threads, 8 outputs/thread.
// ---------------------------------------------------------------------------
__global__ void __launch_bounds__(256) k_rowsum(const float* __restrict__ img) {
    int i = blockIdx.x;
    int j0 = threadIdx.x * 8;
    const float* row = img + (size_t)i * Wd;

    float v[24];  // v[x] = img[i][j0-16+x]
    if (j0 >= 16) {
        const float4* p = (const float4*)(row + j0 - 16);
        #pragma unroll
        for (int q = 0; q < 6; q++) {
            float4 f = __ldg(p + q);
            v[4 * q + 0] = f.x; v[4 * q + 1] = f.y;
            v[4 * q + 2] = f.z; v[4 * q + 3] = f.w;
        }
    } else {
        #pragma unroll
        for (int x = 0; x < 24; x++) {
            int c = j0 - 16 + x;
            v[x] = (c >= 0) ? __ldg(row + c) : 0.f;
        }
    }

    float s = 0.f;
    #pragma unroll
    for (int x = 1; x <= 15; x++) s += v[x];
    float o[8];
    o[0] = s;
    #pragma unroll
    for (int c = 1; c < 8; c++) { s += v[15 + c] - v[c]; o[c] = s; }

    float4* outp = (float4*)(g_rowsum + (size_t)i * Wd + j0);
    outp[0] = make_float4(o[0], o[1], o[2], o[3]);
    outp[1] = make_float4(o[4], o[5], o[6], o[7]);
}

// ---------------------------------------------------------------------------
// Kernel B: vertical sliding 15-sum.
// win[i][j] = sum_{t=1..15} rowsum[i-t][j]   (zero for i-t < 0)
// Each thread: 4 columns (float4) x 16 rows, register ring of 15 float4.
// blockDim = 128, grid = (4, 128).
// ---------------------------------------------------------------------------
__global__ void __launch_bounds__(128) k_colsum() {
    int c0 = 4 * (blockIdx.x * blockDim.x + threadIdx.x);
    int i0 = blockIdx.y * 16;

    float4 buf[15];
    float4 s = make_float4(0.f, 0.f, 0.f, 0.f);
    #pragma unroll
    for (int t = 0; t < 15; t++) {
        int r = i0 - 15 + t;
        float4 f = make_float4(0.f, 0.f, 0.f, 0.f);
        if (r >= 0) f = *(const float4*)(g_rowsum + (size_t)r * Wd + c0);
        buf[t] = f;
        s.x += f.x; s.y += f.y; s.z += f.z; s.w += f.w;
    }
    #pragma unroll
    for (int r = 0; r < 16; r++) {
        *(float4*)(g_win + (size_t)(i0 + r) * Wd + c0) = s;
        if (r < 15) {
            float4 f = *(const float4*)(g_rowsum + (size_t)(i0 + r) * Wd + c0);
            s.x += f.x - buf[r].x;
            s.y += f.y - buf[r].y;
            s.z += f.z - buf[r].z;
            s.w += f.w - buf[r].w;
            buf[r] = f;
        }
    }
}

// ---------------------------------------------------------------------------
// Kernel C: out[i,j] = C + (1/3375) * sum_m w_m * win[(i-sy_m)&M][(j-sx_m)&M]
// Tile 32 rows x 128 cols; halo +-8 staged in SMEM (48 x 144).
// grid = (16, 64), 256 threads; thread = 1 col x 16 rows.
// ---------------------------------------------------------------------------
__global__ void __launch_bounds__(256, 6) k_gather(float* __restrict__ out) {
    __shared__ float tile[48][144];
    __shared__ int ssy[Kk], ssx[Kk];
    __shared__ float sw[Kk];
    __shared__ int sn;
    __shared__ float sC;

    int t = threadIdx.x;
    int j0 = blockIdx.x * 128;
    int i0 = blockIdx.y * 32;

    if (t < Kk) { ssy[t] = g_osy[t]; ssx[t] = g_osx[t]; sw[t] = g_ow[t]; }
    if (t == 0) { sn = g_n; sC = g_C; }

    // stage 48 x 144 halo tile, float4 (alignment safe: j0-8 ≡ 0 mod 4,
    // aligned gc<=2044 so a float4 never crosses the wrap)
    for (int idx = t; idx < 48 * 36; idx += 256) {
        int u  = idx / 36;
        int vq = idx - u * 36;
        int gr = (i0 - 8 + u) & MASKM;
        int gc = (j0 - 8 + 4 * vq) & MASKM;
        float4 f = __ldg((const float4*)(g_win + (size_t)gr * Wd + gc));
        *(float4*)&tile[u][4 * vq] = f;
    }
    __syncthreads();

    int tx = t & 127;          // column
    int R0 = (t >> 7) * 16;    // 0 or 16

    float acc[16];
    #pragma unroll
    for (int rr = 0; rr < 16; rr++) acc[rr] = 0.f;

    int n = sn;
    for (int m = 0; m < n; m++) {
        int sy = ssy[m], sx = ssx[m];
        float w = sw[m];
        if (sy >= -8 && sy <= 8 && sx >= -8 && sx <= 8) {
            const float* p = &tile[R0 + 8 - sy][8 - sx + tx];
            #pragma unroll
            for (int rr = 0; rr < 16; rr++) acc[rr] += w * p[rr * 144];
        } else {
            int gc = (j0 + tx - sx) & MASKM;
            #pragma unroll 1
            for (int rr = 0; rr < 16; rr++) {
                int gr = (i0 + R0 + rr - sy) & MASKM;
                acc[rr] += w * __ldg(g_win + (size_t)gr * Wd + gc);
            }
        }
    }

    const float scale = 1.0f / 3375.0f;
    float c = sC;
    float* op = out + (size_t)(i0 + R0) * Wd + j0 + tx;
    #pragma unroll
    for (int rr = 0; rr < 16; rr++)
        op[(size_t)rr * Wd] = c + scale * acc[rr];
}

// ---------------------------------------------------------------------------
extern "C" void kernel_launch(void* const* d_in, const int* in_sizes, int n_in,
                              void* d_out, int out_size) {
    const float* x        = (const float*)d_in[0];  // (1,1,2048,2048)
    const float* patterns = (const float*)d_in[1];  // (16,15,15)
    const float* vectors  = (const float*)d_in[2];  // (16,2)
    float* out = (float*)d_out;                     // (2048,2048)

    k_prep<<<1, 1024>>>(patterns, vectors);
    k_rowsum<<<Hh, 256>>>(x);
    k_colsum<<<dim3(4, 128), 128>>>();
    k_gather<<<dim3(16, 64), 256>>>(out);
}

// round 4
// speedup vs baseline: 1.5476x; 1.4944x over previous
#include <cuda_runtime.h>
#include <math.h>

#define Hh 2048
#define Wd 2048
#define MASKM 2047
#define Kk 16
#define Pp 15
#define TSTRIDE 144   // gather halo tile row stride

// scratch (static device globals — no allocation)
__device__ float g_win[Hh * Wd];
__device__ float g_C;
__device__ int   g_dfast[Kk];   // smem-relative deltas (padded to 16, w=0)
__device__ float g_wfast[Kk];
__device__ int   g_ng;          // count of out-of-range shifts (rare, ~0)
__device__ int   g_gsy[Kk], g_gsx[Kk];
__device__ float g_gw[Kk];

// ---------------------------------------------------------------------------
// Kernel 0: reduce patterns -> C; dedupe shifts; build branch-free fast list.
// All global loads parallel; serial work touches only SMEM/registers.
// ---------------------------------------------------------------------------
__global__ void __launch_bounds__(1024) k_prep(const float* __restrict__ patterns,
                                               const float* __restrict__ vectors) {
    __shared__ float red[1024];
    __shared__ int shy[Kk], shx[Kk];
    int t = threadIdx.x;

    if (t < Kk) {
        float vy = __ldg(vectors + 2 * t);
        float vx = __ldg(vectors + 2 * t + 1);
        int ny = ((int)floorf(vy)) & MASKM; if (ny >= 1024) ny -= 2048;
        int nx = ((int)floorf(vx)) & MASKM; if (nx >= 1024) nx -= 2048;
        shy[t] = ny; shx[t] = nx;
    }

    float s = 0.f;
    if (t < 900) {  // 3600 floats = 900 float4
        float4 f = __ldg((const float4*)patterns + t);
        s = f.x + f.y + f.z + f.w;
    }
    red[t] = s;
    __syncthreads();
    for (int off = 512; off > 0; off >>= 1) {
        if (t < off) red[t] += red[t + off];
        __syncthreads();
    }

    if (t == 0) {
        g_C = ((float)Kk - red[0] / (float)(Pp * Pp)) / (float)(Kk - 1);
        // dedupe
        int n = 0, sy[Kk], sx[Kk]; float w[Kk];
        #pragma unroll
        for (int k = 0; k < Kk; k++) {
            int ny = shy[k], nx = shx[k], found = -1;
            for (int m = 0; m < n; m++)
                if (sy[m] == ny && sx[m] == nx) { found = m; break; }
            if (found >= 0) w[found] += 1.0f;
            else { sy[n] = ny; sx[n] = nx; w[n] = 1.0f; n++; }
        }
        // split: in-range (|s|<=8) -> fast deltas, else -> rare global list
        int nf = 0, ng = 0;
        for (int m = 0; m < n; m++) {
            if (sy[m] >= -8 && sy[m] <= 8 && sx[m] >= -8 && sx[m] <= 8) {
                g_dfast[nf] = -sy[m] * TSTRIDE - sx[m];
                g_wfast[nf] = w[m];
                nf++;
            } else {
                g_gsy[ng] = sy[m]; g_gsx[ng] = sx[m]; g_gw[ng] = w[m]; ng++;
            }
        }
        for (; nf < Kk; nf++) { g_dfast[nf] = 0; g_wfast[nf] = 0.f; }
        g_ng = ng;
    }
}

// ---------------------------------------------------------------------------
// Kernel 1: fused separable 15x15 box-sum (zero-padded above/left).
// win[i][j] = sum_{a=i-15..i-1, b=j-15..j-1} img[a][b]
// Tile: 128 rows x 64 cols per block; rowsum staged in SMEM (143 x 64,
// stride 65). grid = (32, 16), 256 threads. (Measured ~2-4us in R2.)
// ---------------------------------------------------------------------------
__global__ void __launch_bounds__(256) k_box(const float* __restrict__ img) {
    __shared__ float rs[143 * 65];

    int t = threadIdx.x;
    int j0 = blockIdx.x * 64;
    int i0 = blockIdx.y * 128;

    // phase 1: horizontal sliding sum into rs
    for (int tt = t; tt < 143 * 8; tt += 256) {
        int r   = tt >> 3;
        int seg = tt & 7;
        int arow = i0 - 15 + r;
        int jb = j0 + seg * 8;
        float o[8];
        if (arow < 0) {
            #pragma unroll
            for (int c = 0; c < 8; c++) o[c] = 0.f;
        } else {
            const float* row = img + (size_t)arow * Wd;
            float v[24];
            if (jb >= 16) {
                const float4* p = (const float4*)(row + jb - 16);
                #pragma unroll
                for (int q = 0; q < 6; q++) {
                    float4 f = __ldg(p + q);
                    v[4 * q + 0] = f.x; v[4 * q + 1] = f.y;
                    v[4 * q + 2] = f.z; v[4 * q + 3] = f.w;
                }
            } else {
                #pragma unroll
                for (int x = 0; x < 24; x++) {
                    int c = jb - 16 + x;
                    v[x] = (c >= 0) ? __ldg(row + c) : 0.f;
                }
            }
            float s = 0.f;
            #pragma unroll
            for (int x = 1; x <= 15; x++) s += v[x];
            o[0] = s;
            #pragma unroll
            for (int c = 1; c < 8; c++) { s += v[15 + c] - v[c]; o[c] = s; }
        }
        float* dst = rs + r * 65 + seg * 8;
        #pragma unroll
        for (int c = 0; c < 8; c++) dst[c] = o[c];
    }
    __syncthreads();

    // phase 2: vertical sliding sum -> win
    int col = t & 63;
    int R0  = (t >> 6) * 32;
    const float* cp = rs + col;
    float s = 0.f;
    #pragma unroll
    for (int r = 0; r < 15; r++) s += cp[(R0 + r) * 65];
    float* outp = g_win + (size_t)(i0 + R0) * Wd + j0 + col;
    #pragma unroll
    for (int rr = 0; rr < 32; rr++) {
        outp[(size_t)rr * Wd] = s;
        if (rr < 31)
            s += cp[(R0 + rr + 15) * 65] - cp[(R0 + rr) * 65];
    }
}

// ---------------------------------------------------------------------------
// Kernel 2: out[i,j] = C + (1/3375)*sum_m w_m * win[(i-sy)&M][(j-sx)&M]
// 64x128 tile/block; 80x144 halo in SMEM (46KB). Branch-free fully-unrolled
// 16-entry fast loop (zero-weight padding); rare uniform global fallback.
// grid = (16, 32), 256 threads; thread = 1 col x 32 rows.
// ---------------------------------------------------------------------------
__global__ void __launch_bounds__(256) k_gather(float* __restrict__ out) {
    __shared__ float tile[80 * TSTRIDE];
    __shared__ int   sd[Kk];
    __shared__ float sw[Kk];
    __shared__ int   sng;
    __shared__ float sC;

    int t = threadIdx.x;
    int j0 = blockIdx.x * 128;
    int i0 = blockIdx.y * 64;

    if (t < Kk) { sd[t] = g_dfast[t]; sw[t] = g_wfast[t]; }
    if (t == 0) { sng = g_ng; sC = g_C; }

    // stage 80 x 144 halo via float4 (j0-8 ≡ 0 mod 4; wrap never splits)
    for (int idx = t; idx < 80 * 36; idx += 256) {
        int u  = idx / 36;
        int vq = idx - u * 36;
        int gr = (i0 - 8 + u) & MASKM;
        int gc = (j0 - 8 + 4 * vq) & MASKM;
        float4 f = __ldg((const float4*)(g_win + (size_t)gr * Wd + gc));
        *(float4*)&tile[u * TSTRIDE + 4 * vq] = f;
    }
    __syncthreads();

    int tx = t & 127;
    int R0 = (t >> 7) * 32;   // 0 or 32
    const float* base = tile + (R0 + 8) * TSTRIDE + tx + 8;

    float acc[32];
    #pragma unroll
    for (int rr = 0; rr < 32; rr++) acc[rr] = 0.f;

    #pragma unroll
    for (int m = 0; m < Kk; m++) {
        float w = sw[m];
        const float* p = base + sd[m];
        #pragma unroll
        for (int rr = 0; rr < 32; rr++)
            acc[rr] += w * p[rr * TSTRIDE];
    }

    int ng = sng;
    if (ng > 0) {  // uniform, essentially never taken
        for (int m = 0; m < ng; m++) {
            int sy = g_gsy[m], sx = g_gsx[m];
            float w = g_gw[m];
            int gc = (j0 + tx - sx) & MASKM;
            #pragma unroll 1
            for (int rr = 0; rr < 32; rr++) {
                int gr = (i0 + R0 + rr - sy) & MASKM;
                acc[rr] += w * __ldg(g_win + (size_t)gr * Wd + gc);
            }
        }
    }

    const float scale = 1.0f / 3375.0f;
    float c = sC;
    float* op = out + (size_t)(i0 + R0) * Wd + j0 + tx;
    #pragma unroll
    for (int rr = 0; rr < 32; rr++)
        op[(size_t)rr * Wd] = c + scale * acc[rr];
}

// ---------------------------------------------------------------------------
extern "C" void kernel_launch(void* const* d_in, const int* in_sizes, int n_in,
                              void* d_out, int out_size) {
    const float* x        = (const float*)d_in[0];  // (1,1,2048,2048)
    const float* patterns = (const float*)d_in[1];  // (16,15,15)
    const float* vectors  = (const float*)d_in[2];  // (16,2)
    float* out = (float*)d_out;                     // (2048,2048)

    k_prep<<<1, 1024>>>(patterns, vectors);
    k_box<<<dim3(32, 16), 256>>>(x);
    k_gather<<<dim3(16, 32), 256>>>(out);
}